// round 2
// baseline (speedup 1.0000x reference)
#include <cuda_runtime.h>
#include <cstddef>

#define BB 2048
#define NN 128
#define DD 512

// 8 MB scratch for cw = content @ cow, rows interleaved: row 2b = text[b]@cow, 2b+1 = img[b]@cow
__device__ float g_cw[(size_t)2 * BB * DD];

// ---------------------------------------------------------------------------
// f32x2 packed helpers (FFMA2 — only reachable via PTX fma.rn.f32x2)
// ---------------------------------------------------------------------------
__device__ __forceinline__ float2 ffma2(float2 a, float2 b, float2 c) {
  float2 d;
  asm("fma.rn.f32x2 %0, %1, %2, %3;"
      : "=l"(*reinterpret_cast<unsigned long long*>(&d))
      : "l"(*reinterpret_cast<const unsigned long long*>(&a)),
        "l"(*reinterpret_cast<const unsigned long long*>(&b)),
        "l"(*reinterpret_cast<const unsigned long long*>(&c)));
  return d;
}
__device__ __forceinline__ float2 fmul2(float2 a, float2 b) {
  float2 d;
  asm("mul.rn.f32x2 %0, %1, %2;"
      : "=l"(*reinterpret_cast<unsigned long long*>(&d))
      : "l"(*reinterpret_cast<const unsigned long long*>(&a)),
        "l"(*reinterpret_cast<const unsigned long long*>(&b)));
  return d;
}
__device__ __forceinline__ float tanh_fast(float x) {
  float y;
  asm("tanh.approx.f32 %0, %1;" : "=f"(y) : "f"(x));
  return y;
}

// ---------------------------------------------------------------------------
// Kernel 1: cw[r][d] = sum_e A[r][e] * cow[e][d],  A row r: (r&1)? img[r>>1] : text[r>>1]
// BM=64, BN=128, BK=16, 256 threads, 4x8 microtile, double-buffered smem, FFMA2.
// ---------------------------------------------------------------------------
#define GBM 64
#define GBN 128
#define GBK 16

__global__ __launch_bounds__(256) void gemm_cw_kernel(
    const float* __restrict__ text, const float* __restrict__ img,
    const float* __restrict__ cow) {
  __shared__ __align__(16) float As[2][GBK][GBM];
  __shared__ __align__(16) float Bs[2][GBK][GBN];
  const int tid = threadIdx.x;
  const int tx = tid & 15;   // 16 cols of threads, 8 outputs each
  const int ty = tid >> 4;   // 16 rows of threads, 4 outputs each
  const int m0 = blockIdx.y * GBM;
  const int n0 = blockIdx.x * GBN;

  const int arow = tid >> 2, ac4 = tid & 3;
  const int r = m0 + arow;
  const float* asrc = ((r & 1) ? img : text) + (size_t)(r >> 1) * DD + ac4 * 4;
  const int b0row = tid >> 5, b0c = (tid & 31) * 4;
  const int b1row = b0row + 8, b1c = b0c;

  float2 acc[4][4];
#pragma unroll
  for (int i = 0; i < 4; i++)
#pragma unroll
    for (int j = 0; j < 4; j++) acc[i][j] = make_float2(0.f, 0.f);

  float4 aReg, bReg0, bReg1;
  // prologue: tile 0 -> buf 0
  aReg = *(const float4*)(asrc);
  bReg0 = *(const float4*)(cow + (size_t)b0row * DD + n0 + b0c);
  bReg1 = *(const float4*)(cow + (size_t)b1row * DD + n0 + b1c);
  As[0][ac4 * 4 + 0][arow] = aReg.x;
  As[0][ac4 * 4 + 1][arow] = aReg.y;
  As[0][ac4 * 4 + 2][arow] = aReg.z;
  As[0][ac4 * 4 + 3][arow] = aReg.w;
  *(float4*)&Bs[0][b0row][b0c] = bReg0;
  *(float4*)&Bs[0][b1row][b1c] = bReg1;
  __syncthreads();

  const int NT = DD / GBK;  // 32
  for (int t = 0; t < NT; t++) {
    const int cur = t & 1;
    if (t + 1 < NT) {
      const int kk = (t + 1) * GBK;
      aReg = *(const float4*)(asrc + kk);
      bReg0 = *(const float4*)(cow + (size_t)(kk + b0row) * DD + n0 + b0c);
      bReg1 = *(const float4*)(cow + (size_t)(kk + b1row) * DD + n0 + b1c);
    }
#pragma unroll
    for (int k = 0; k < GBK; k++) {
      float4 av = *(const float4*)&As[cur][k][ty * 4];
      float4 b0 = *(const float4*)&Bs[cur][k][tx * 8];
      float4 b1 = *(const float4*)&Bs[cur][k][tx * 8 + 4];
      float2 bb[4] = {make_float2(b0.x, b0.y), make_float2(b0.z, b0.w),
                      make_float2(b1.x, b1.y), make_float2(b1.z, b1.w)};
      float a_[4] = {av.x, av.y, av.z, av.w};
#pragma unroll
      for (int i = 0; i < 4; i++) {
        float2 ap = make_float2(a_[i], a_[i]);
#pragma unroll
        for (int j = 0; j < 4; j++) acc[i][j] = ffma2(ap, bb[j], acc[i][j]);
      }
    }
    if (t + 1 < NT) {
      const int nxt = cur ^ 1;
      As[nxt][ac4 * 4 + 0][arow] = aReg.x;
      As[nxt][ac4 * 4 + 1][arow] = aReg.y;
      As[nxt][ac4 * 4 + 2][arow] = aReg.z;
      As[nxt][ac4 * 4 + 3][arow] = aReg.w;
      *(float4*)&Bs[nxt][b0row][b0c] = bReg0;
      *(float4*)&Bs[nxt][b1row][b1c] = bReg1;
      __syncthreads();
    }
  }

#pragma unroll
  for (int i = 0; i < 4; i++) {
    const int rr = m0 + ty * 4 + i;
    float4 o0 = make_float4(acc[i][0].x, acc[i][0].y, acc[i][1].x, acc[i][1].y);
    float4 o1 = make_float4(acc[i][2].x, acc[i][2].y, acc[i][3].x, acc[i][3].y);
    *(float4*)&g_cw[(size_t)rr * DD + n0 + tx * 8] = o0;
    *(float4*)&g_cw[(size_t)rr * DD + n0 + tx * 8 + 4] = o1;
  }
}

// ---------------------------------------------------------------------------
// Kernel 2: fused co-attention. One CTA/sample, 8 warps, warp processes PAIRS
// of comments (n, n+8) per iteration -> 8 LDG.128 in flight; online softmax.
// ---------------------------------------------------------------------------
__global__ __launch_bounds__(256, 2) void fusion_kernel(
    const float* __restrict__ text, const float* __restrict__ img,
    const float* __restrict__ comment, const int* __restrict__ cnum,
    const float* __restrict__ W_ca, const float* __restrict__ b_ca,
    const float* __restrict__ W_co, const float* __restrict__ b_co,
    float* __restrict__ out) {
  const int b = blockIdx.x;
  const int tid = threadIdx.x;
  const int wid = tid >> 5;
  const int lane = tid & 31;

  __shared__ __align__(16) float s_c0[DD], s_c1[DD], s_wca[DD], s_wco[DD];
  __shared__ __align__(16) float s_acc0[DD], s_acc1[DD], s_accz[DD];
  __shared__ float s_m[8], s_s[8], s_r0[8], s_r1[8];

  for (int i = tid; i < DD; i += 256) {
    s_c0[i] = text[(size_t)b * DD + i];
    s_c1[i] = img[(size_t)b * DD + i];
    s_wca[i] = W_ca[i];
    s_wco[i] = W_co[i];
    s_acc0[i] = 0.f;
    s_acc1[i] = 0.f;
    s_accz[i] = 0.f;
  }
  const int cnt = cnum[b];
  const float bca = b_ca[0], bco = b_co[0];
  __syncthreads();

  // cw rows register-resident: lane owns float4 slots lane+32*jj (jj=0..3),
  // i.e. d = 4*(lane+32*jj) + c. As float2: [2*jj], [2*jj+1].
  float2 cw0r[8], cw1r[8];
  {
    const float4* p0 = (const float4*)(g_cw + (size_t)(2 * b) * DD);
    const float4* p1 = (const float4*)(g_cw + (size_t)(2 * b + 1) * DD);
#pragma unroll
    for (int jj = 0; jj < 4; jj++) {
      float4 t0 = p0[lane + 32 * jj];
      float4 t1 = p1[lane + 32 * jj];
      cw0r[2 * jj] = make_float2(t0.x, t0.y);
      cw0r[2 * jj + 1] = make_float2(t0.z, t0.w);
      cw1r[2 * jj] = make_float2(t1.x, t1.y);
      cw1r[2 * jj + 1] = make_float2(t1.z, t1.w);
    }
  }

  const float4* c04 = (const float4*)s_c0;
  const float4* c14 = (const float4*)s_c1;
  const float4* wco4 = (const float4*)s_wco;

  float mrun = -INFINITY, ssum = 0.f;
  float2 az[8], a0[8], a1[8];
#pragma unroll
  for (int j = 0; j < 8; j++) {
    az[j] = make_float2(0.f, 0.f);
    a0[j] = make_float2(0.f, 0.f);
    a1[j] = make_float2(0.f, 0.f);
  }

  auto load_z = [&](int n, float2 (&zv)[8]) {
    const float4* zp = (const float4*)(comment + ((size_t)b * NN + n) * DD);
#pragma unroll
    for (int jj = 0; jj < 4; jj++) {
      float4 t = zp[lane + 32 * jj];
      zv[2 * jj] = make_float2(t.x, t.y);
      zv[2 * jj + 1] = make_float2(t.z, t.w);
    }
  };

  auto process = [&](const float2 (&zv)[8]) {
    // co_w dots (f32x2 then horizontal + butterfly)
    float2 d0 = make_float2(0.f, 0.f), d1 = make_float2(0.f, 0.f);
#pragma unroll
    for (int j = 0; j < 8; j++) {
      d0 = ffma2(zv[j], cw0r[j], d0);
      d1 = ffma2(zv[j], cw1r[j], d1);
    }
    float s0 = d0.x + d0.y, s1 = d1.x + d1.y;
#pragma unroll
    for (int off = 16; off > 0; off >>= 1) {
      s0 += __shfl_xor_sync(0xffffffffu, s0, off);
      s1 += __shfl_xor_sync(0xffffffffu, s1, off);
    }
    const float w0 = tanh_fast(s0);
    const float w1 = tanh_fast(s1);
    const float2 w0p = make_float2(w0, w0);
    const float2 w1p = make_float2(w1, w1);

    // zw logit: W_co . tanh(z + w0*c0 + w1*c1)
    float pz = 0.f;
#pragma unroll
    for (int jj = 0; jj < 4; jj++) {
      float4 c0v = c04[lane + 32 * jj];
      float4 c1v = c14[lane + 32 * jj];
      float4 wv = wco4[lane + 32 * jj];
      float2 tA = ffma2(w0p, make_float2(c0v.x, c0v.y), zv[2 * jj]);
      tA = ffma2(w1p, make_float2(c1v.x, c1v.y), tA);
      float2 tB = ffma2(w0p, make_float2(c0v.z, c0v.w), zv[2 * jj + 1]);
      tB = ffma2(w1p, make_float2(c1v.z, c1v.w), tB);
      pz += wv.x * tanh_fast(tA.x);
      pz += wv.y * tanh_fast(tA.y);
      pz += wv.z * tanh_fast(tB.x);
      pz += wv.w * tanh_fast(tB.y);
    }
#pragma unroll
    for (int off = 16; off > 0; off >>= 1) pz += __shfl_xor_sync(0xffffffffu, pz, off);
    const float l = pz + bco;

    // online softmax (l warp-uniform)
    const float mnew = fmaxf(mrun, l);
    const float fac = __expf(mrun - mnew);
    const float pe = __expf(l - mnew);
    ssum = ssum * fac + pe;
    const float2 facp = make_float2(fac, fac);
    const float2 pep = make_float2(pe, pe);
    if (fac != 1.f) {
#pragma unroll
      for (int j = 0; j < 8; j++) az[j] = fmul2(az[j], facp);
    }
#pragma unroll
    for (int j = 0; j < 8; j++) {
      az[j] = ffma2(pep, zv[j], az[j]);
      a0[j] = ffma2(w0p, zv[j], a0[j]);
      a1[j] = ffma2(w1p, zv[j], a1[j]);
    }
    mrun = mnew;
  };

  int n = wid;
  for (; n + 8 < cnt; n += 16) {
    float2 zA[8], zB[8];
    load_z(n, zA);       // 8 LDG.128 in flight before any compute
    load_z(n + 8, zB);
    process(zA);
    process(zB);
  }
  if (n < cnt) {
    float2 zA[8];
    load_z(n, zA);
    process(zA);
  }

  if (lane == 0) { s_m[wid] = mrun; s_s[wid] = ssum; }
  __syncthreads();

  float M = s_m[0];
#pragma unroll
  for (int w = 1; w < 8; w++) M = fmaxf(M, s_m[w]);
  float S = 0.f;
#pragma unroll
  for (int w = 0; w < 8; w++) S += s_s[w] * __expf(s_m[w] - M);
  const float rsc = __expf(mrun - M);  // warp rescale (0 if warp had no rows)

  // deterministic serialized merge of per-warp accumulators into smem
  float4* acc04 = (float4*)s_acc0;
  float4* acc14 = (float4*)s_acc1;
  float4* accz4 = (float4*)s_accz;
  for (int w = 0; w < 8; w++) {
    if (wid == w) {
#pragma unroll
      for (int jj = 0; jj < 4; jj++) {
        const int idx = lane + 32 * jj;
        float4 t0 = acc04[idx];
        t0.x += a0[2 * jj].x; t0.y += a0[2 * jj].y;
        t0.z += a0[2 * jj + 1].x; t0.w += a0[2 * jj + 1].y;
        acc04[idx] = t0;
        float4 t1 = acc14[idx];
        t1.x += a1[2 * jj].x; t1.y += a1[2 * jj].y;
        t1.z += a1[2 * jj + 1].x; t1.w += a1[2 * jj + 1].y;
        acc14[idx] = t1;
        float4 tz = accz4[idx];
        tz.x += rsc * az[2 * jj].x; tz.y += rsc * az[2 * jj].y;
        tz.z += rsc * az[2 * jj + 1].x; tz.w += rsc * az[2 * jj + 1].y;
        accz4[idx] = tz;
      }
    }
    __syncthreads();
  }

  // content attention logits + 2-way softmax
  float p0 = 0.f, p1 = 0.f;
  for (int i = tid; i < DD; i += 256) {
    p0 += s_wca[i] * tanh_fast(s_c0[i] + s_acc0[i]);
    p1 += s_wca[i] * tanh_fast(s_c1[i] + s_acc1[i]);
  }
#pragma unroll
  for (int off = 16; off > 0; off >>= 1) {
    p0 += __shfl_xor_sync(0xffffffffu, p0, off);
    p1 += __shfl_xor_sync(0xffffffffu, p1, off);
  }
  if (lane == 0) { s_r0[wid] = p0; s_r1[wid] = p1; }
  __syncthreads();
  float l0 = bca, l1 = bca;
#pragma unroll
  for (int w = 0; w < 8; w++) { l0 += s_r0[w]; l1 += s_r1[w]; }
  const float mx = fmaxf(l0, l1);
  const float e0 = __expf(l0 - mx);
  const float e1 = __expf(l1 - mx);
  const float inv2 = 1.f / (e0 + e1);
  const float cwt0 = e0 * inv2;
  const float cwt1 = e1 * inv2;

  float* out_rc = out;
  float* out_rcm = out + (size_t)BB * DD;
  float* out_cw = out + (size_t)2 * BB * DD;
  if (tid == 0) {
    out_cw[2 * b] = cwt0;
    out_cw[2 * b + 1] = cwt1;
  }
  const float invS = 1.f / S;
  for (int i = tid; i < DD; i += 256) {
    out_rc[(size_t)b * DD + i] = s_c0[i] * cwt0 + s_c1[i] * cwt1;
    out_rcm[(size_t)b * DD + i] = s_accz[i] * invS;
  }
}

// ---------------------------------------------------------------------------
extern "C" void kernel_launch(void* const* d_in, const int* in_sizes, int n_in,
                              void* d_out, int out_size) {
  const float* text = (const float*)d_in[0];
  const float* img = (const float*)d_in[1];
  const float* comment = (const float*)d_in[2];
  const int* cnum = (const int*)d_in[3];
  const float* cow = (const float*)d_in[4];
  const float* W_ca = (const float*)d_in[5];
  const float* b_ca = (const float*)d_in[6];
  const float* W_co = (const float*)d_in[7];
  const float* b_co = (const float*)d_in[8];
  float* out = (float*)d_out;

  dim3 ggrid(DD / GBN, (2 * BB) / GBM);  // (4, 64) = 256 CTAs
  gemm_cw_kernel<<<ggrid, 256>>>(text, img, cow);
  fusion_kernel<<<BB, 256>>>(text, img, comment, cnum, W_ca, b_ca, W_co, b_co, out);
}